// round 8
// baseline (speedup 1.0000x reference)
#include <cuda_runtime.h>
#include <cstdint>

#define N_NODES 100000
#define N_EDGES 1600000
#define DIM     128

// ---------------- scratch (no allocations allowed) ----------------
__device__ int g_deg[N_NODES];
__device__ int g_rowptr[N_NODES + 1];
__device__ int g_wcur[N_NODES];
__device__ int g_esrc[N_EDGES];
__device__ __align__(16) float g_bufA[(size_t)N_NODES * DIM];
__device__ __align__(16) float g_bufB[(size_t)N_NODES * DIM];

// ---------------- CSR build ----------------
__global__ void zero_deg_kernel() {
    int i = blockIdx.x * blockDim.x + threadIdx.x;
    if (i < N_NODES) g_deg[i] = 0;
}

__global__ void count_kernel(const int* __restrict__ ei) {
    int e = blockIdx.x * blockDim.x + threadIdx.x;
    if (e < N_EDGES) atomicAdd(&g_deg[ei[N_EDGES + e]], 1);
}

__global__ void scan_kernel() {
    __shared__ int s[1024];
    int tid = threadIdx.x;
    const int per = (N_NODES + 1023) / 1024;
    int start = tid * per;
    int end = min(start + per, N_NODES);
    int sum = 0;
    for (int i = start; i < end; i++) sum += g_deg[i];
    s[tid] = sum;
    __syncthreads();
    #pragma unroll
    for (int off = 1; off < 1024; off <<= 1) {
        int v = (tid >= off) ? s[tid - off] : 0;
        __syncthreads();
        s[tid] += v;
        __syncthreads();
    }
    int run = (tid == 0) ? 0 : s[tid - 1];
    for (int i = start; i < end; i++) {
        g_rowptr[i] = run;
        g_wcur[i]   = run;
        run += g_deg[i];
    }
    if (tid == 0) g_rowptr[N_NODES] = s[1023];
}

__global__ void fill_kernel(const int* __restrict__ ei) {
    int e = blockIdx.x * blockDim.x + threadIdx.x;
    if (e < N_EDGES) {
        int d = ei[N_EDGES + e];
        int pos = atomicAdd(&g_wcur[d], 1);
        g_esrc[pos] = ei[e];
    }
}

// ================= fused gather + mma.sync tf32 MLP =================
// Per 128-row tile: each warp CSR-aggregates its 16 rows straight into sH,
// then the block runs D1 = relu(A@W1+b1) and D2 = D1@W2+b2 (+relu) -> gmem.
// Warp MMA partition: 2 m16-slabs x 8 n8-frags (B frags reused across slabs).
#define W_STRIDE 132
#define SM_H   0
#define SM_W1  (128 * W_STRIDE * 4)
#define SM_W2  (2 * 128 * W_STRIDE * 4)
#define SM_B   (3 * 128 * W_STRIDE * 4)
#define MLP_SMEM (SM_B + 1024)

__device__ __forceinline__ uint32_t f2tf32(float f) {
    uint32_t r;
    asm("cvt.rna.tf32.f32 %0, %1;" : "=r"(r) : "f"(f));
    return r;
}

__device__ __forceinline__ void mma16n8k8(float* c,
                                          uint32_t a0, uint32_t a1, uint32_t a2, uint32_t a3,
                                          uint32_t b0, uint32_t b1) {
    asm volatile(
        "mma.sync.aligned.m16n8k8.row.col.f32.tf32.tf32.f32 "
        "{%0,%1,%2,%3}, {%4,%5,%6,%7}, {%8,%9}, {%0,%1,%2,%3};"
        : "+f"(c[0]), "+f"(c[1]), "+f"(c[2]), "+f"(c[3])
        : "r"(a0), "r"(a1), "r"(a2), "r"(a3), "r"(b0), "r"(b1));
}

__global__ void __launch_bounds__(256, 1)
gin_fused(const float4* __restrict__ xin,
          const float* __restrict__ W1, const float* __restrict__ b1,
          const float* __restrict__ W2, const float* __restrict__ b2,
          float* __restrict__ out, int relu_out)
{
    extern __shared__ __align__(16) char sm[];
    float*    sH  = (float*)(sm + SM_H);
    uint32_t* sW1 = (uint32_t*)(sm + SM_W1);
    uint32_t* sW2 = (uint32_t*)(sm + SM_W2);
    float*    sB1 = (float*)(sm + SM_B);
    float*    sB2 = sB1 + 128;

    const int tid  = threadIdx.x;
    const int wid  = tid >> 5;
    const int lane = tid & 31;
    const int gid  = lane >> 2;   // 0..7
    const int tig  = lane & 3;    // 0..3
    const int fh   = wid & 1;     // n half: fh*64
    const int sp   = wid >> 1;    // slab pair: rows sp*32 .. sp*32+31
    const int nbase = fh * 64;
    const int mbase = sp * 32;
    const int gr_base = wid * 16; // gather rows owned by this warp

    for (int i = tid; i < 16384; i += 256) {
        int k = i >> 7, n = i & 127;
        sW1[k * W_STRIDE + n] = f2tf32(W1[i]);
        sW2[k * W_STRIDE + n] = f2tf32(W2[i]);
    }
    if (tid < 128) { sB1[tid] = b1[tid]; sB2[tid] = b2[tid]; }
    __syncthreads();

    const int ntiles = (N_NODES + 127) / 128;
    const float* arow0 = sH + (mbase + gid) * W_STRIDE;
    const float* arow1 = arow0 + 16 * W_STRIDE;

    for (int t = blockIdx.x; t < ntiles; t += gridDim.x) {
        const int row0 = t * 128;

        // ---- gather phase: this warp aggregates its 16 rows into sH ----
        for (int r8 = 0; r8 < 16; r8++) {
            const int node = row0 + gr_base + r8;
            float4 acc = make_float4(0.f, 0.f, 0.f, 0.f);
            if (node < N_NODES) {
                acc = __ldg(&xin[(size_t)node * 32 + lane]);   // self term
                float4 ac1 = make_float4(0.f, 0.f, 0.f, 0.f);
                int e   = g_rowptr[node];
                int end = g_rowptr[node + 1];
                for (; e + 4 <= end; e += 4) {
                    int s0 = g_esrc[e+0], s1 = g_esrc[e+1];
                    int s2 = g_esrc[e+2], s3 = g_esrc[e+3];
                    float4 v0 = __ldg(&xin[(size_t)s0 * 32 + lane]);
                    float4 v1 = __ldg(&xin[(size_t)s1 * 32 + lane]);
                    float4 v2 = __ldg(&xin[(size_t)s2 * 32 + lane]);
                    float4 v3 = __ldg(&xin[(size_t)s3 * 32 + lane]);
                    acc.x += v0.x + v2.x; acc.y += v0.y + v2.y;
                    acc.z += v0.z + v2.z; acc.w += v0.w + v2.w;
                    ac1.x += v1.x + v3.x; ac1.y += v1.y + v3.y;
                    ac1.z += v1.z + v3.z; ac1.w += v1.w + v3.w;
                }
                for (; e < end; e++) {
                    int s0 = g_esrc[e];
                    float4 v0 = __ldg(&xin[(size_t)s0 * 32 + lane]);
                    acc.x += v0.x; acc.y += v0.y; acc.z += v0.z; acc.w += v0.w;
                }
                acc.x += ac1.x; acc.y += ac1.y; acc.z += ac1.z; acc.w += ac1.w;
            }
            *(float4*)(sH + (gr_base + r8) * W_STRIDE + lane * 4) = acc;
        }
        __syncthreads();

        float acc[2][8][4];
        #pragma unroll
        for (int s = 0; s < 2; s++)
            #pragma unroll
            for (int f = 0; f < 8; f++)
                acc[s][f][0] = acc[s][f][1] = acc[s][f][2] = acc[s][f][3] = 0.f;

        // ---- GEMM1 ----
        #pragma unroll 2
        for (int ks = 0; ks < 16; ks++) {
            const int k0 = ks * 8;
            uint32_t a00 = f2tf32(arow0[k0 + tig]);
            uint32_t a01 = f2tf32(arow0[8 * W_STRIDE + k0 + tig]);
            uint32_t a02 = f2tf32(arow0[k0 + tig + 4]);
            uint32_t a03 = f2tf32(arow0[8 * W_STRIDE + k0 + tig + 4]);
            uint32_t a10 = f2tf32(arow1[k0 + tig]);
            uint32_t a11 = f2tf32(arow1[8 * W_STRIDE + k0 + tig]);
            uint32_t a12 = f2tf32(arow1[k0 + tig + 4]);
            uint32_t a13 = f2tf32(arow1[8 * W_STRIDE + k0 + tig + 4]);
            const uint32_t* bk0 = sW1 + (k0 + tig) * W_STRIDE + nbase + gid;
            const uint32_t* bk1 = bk0 + 4 * W_STRIDE;
            #pragma unroll
            for (int f = 0; f < 8; f++) {
                uint32_t b0 = bk0[f * 8], b1 = bk1[f * 8];
                mma16n8k8(acc[0][f], a00, a01, a02, a03, b0, b1);
                mma16n8k8(acc[1][f], a10, a11, a12, a13, b0, b1);
            }
        }

        // ---- epilogue1: relu(acc + b1) -> sH ----
        __syncthreads();
        #pragma unroll
        for (int s = 0; s < 2; s++) {
            int ra = mbase + s * 16 + gid;
            #pragma unroll
            for (int f = 0; f < 8; f++) {
                int col = nbase + 8 * f + 2 * tig;
                float v0 = fmaxf(acc[s][f][0] + sB1[col],     0.f);
                float v1 = fmaxf(acc[s][f][1] + sB1[col + 1], 0.f);
                float v2 = fmaxf(acc[s][f][2] + sB1[col],     0.f);
                float v3 = fmaxf(acc[s][f][3] + sB1[col + 1], 0.f);
                *(float2*)(sH + ra * W_STRIDE + col)       = make_float2(v0, v1);
                *(float2*)(sH + (ra + 8) * W_STRIDE + col) = make_float2(v2, v3);
            }
        }
        __syncthreads();

        #pragma unroll
        for (int s = 0; s < 2; s++)
            #pragma unroll
            for (int f = 0; f < 8; f++)
                acc[s][f][0] = acc[s][f][1] = acc[s][f][2] = acc[s][f][3] = 0.f;

        // ---- GEMM2 ----
        #pragma unroll 2
        for (int ks = 0; ks < 16; ks++) {
            const int k0 = ks * 8;
            uint32_t a00 = f2tf32(arow0[k0 + tig]);
            uint32_t a01 = f2tf32(arow0[8 * W_STRIDE + k0 + tig]);
            uint32_t a02 = f2tf32(arow0[k0 + tig + 4]);
            uint32_t a03 = f2tf32(arow0[8 * W_STRIDE + k0 + tig + 4]);
            uint32_t a10 = f2tf32(arow1[k0 + tig]);
            uint32_t a11 = f2tf32(arow1[8 * W_STRIDE + k0 + tig]);
            uint32_t a12 = f2tf32(arow1[k0 + tig + 4]);
            uint32_t a13 = f2tf32(arow1[8 * W_STRIDE + k0 + tig + 4]);
            const uint32_t* bk0 = sW2 + (k0 + tig) * W_STRIDE + nbase + gid;
            const uint32_t* bk1 = bk0 + 4 * W_STRIDE;
            #pragma unroll
            for (int f = 0; f < 8; f++) {
                uint32_t b0 = bk0[f * 8], b1 = bk1[f * 8];
                mma16n8k8(acc[0][f], a00, a01, a02, a03, b0, b1);
                mma16n8k8(acc[1][f], a10, a11, a12, a13, b0, b1);
            }
        }

        // ---- epilogue2: acc + b2 (+relu) -> gmem ----
        #pragma unroll
        for (int s = 0; s < 2; s++) {
            const int gr0 = row0 + mbase + s * 16 + gid;
            const int gr1 = gr0 + 8;
            #pragma unroll
            for (int f = 0; f < 8; f++) {
                int col = nbase + 8 * f + 2 * tig;
                if (gr0 < N_NODES) {
                    float v0 = acc[s][f][0] + sB2[col];
                    float v1 = acc[s][f][1] + sB2[col + 1];
                    if (relu_out) { v0 = fmaxf(v0, 0.f); v1 = fmaxf(v1, 0.f); }
                    *(float2*)(out + (size_t)gr0 * DIM + col) = make_float2(v0, v1);
                }
                if (gr1 < N_NODES) {
                    float v2 = acc[s][f][2] + sB2[col];
                    float v3 = acc[s][f][3] + sB2[col + 1];
                    if (relu_out) { v2 = fmaxf(v2, 0.f); v3 = fmaxf(v3, 0.f); }
                    *(float2*)(out + (size_t)gr1 * DIM + col) = make_float2(v2, v3);
                }
            }
        }
        __syncthreads();   // protect sH before next tile's gather
    }
}

// ---------------- launch ----------------
extern "C" void kernel_launch(void* const* d_in, const int* in_sizes, int n_in,
                              void* d_out, int out_size)
{
    const float* x  = (const float*)d_in[0];
    const int*   ei = (const int*)d_in[1];
    const float* W1 = (const float*)d_in[2];
    const float* b1 = (const float*)d_in[3];
    const float* W2 = (const float*)d_in[4];
    const float* b2 = (const float*)d_in[5];
    float* out = (float*)d_out;

    static float* bufA = nullptr;
    static float* bufB = nullptr;
    if (!bufA) {
        void *pA, *pB;
        cudaGetSymbolAddress(&pA, g_bufA);
        cudaGetSymbolAddress(&pB, g_bufB);
        bufA = (float*)pA;
        bufB = (float*)pB;
        cudaFuncSetAttribute(gin_fused, cudaFuncAttributeMaxDynamicSharedMemorySize, MLP_SMEM);
    }

    // CSR build
    zero_deg_kernel<<<(N_NODES + 255) / 256, 256>>>();
    count_kernel<<<(N_EDGES + 255) / 256, 256>>>(ei);
    scan_kernel<<<1, 1024>>>();
    fill_kernel<<<(N_EDGES + 255) / 256, 256>>>(ei);

    // fused layers: x -> bufA -> bufB -> out
    gin_fused<<<148, 256, MLP_SMEM>>>((const float4*)x, W1, b1, W2, b2, bufA, 1);
    gin_fused<<<148, 256, MLP_SMEM>>>((const float4*)bufA,
                                      W1 + 16384, b1 + 128, W2 + 16384, b2 + 128, bufB, 1);
    gin_fused<<<148, 256, MLP_SMEM>>>((const float4*)bufB,
                                      W1 + 32768, b1 + 256, W2 + 32768, b2 + 256, out, 0);
}

// round 9
// speedup vs baseline: 1.8301x; 1.8301x over previous
#include <cuda_runtime.h>
#include <cstdint>

#define N_NODES 100000
#define N_EDGES 1600000
#define DIM     128

// ---------------- scratch (no allocations allowed) ----------------
__device__ int g_deg[N_NODES];
__device__ int g_rowptr[N_NODES + 1];
__device__ int g_wcur[N_NODES];
__device__ int g_esrc[N_EDGES];
__device__ __align__(16) float g_bufA[(size_t)N_NODES * DIM];
__device__ __align__(16) float g_bufB[(size_t)N_NODES * DIM];

// ---------------- CSR build ----------------
__global__ void count_kernel(const int* __restrict__ ei) {
    int e = blockIdx.x * blockDim.x + threadIdx.x;
    if (e < N_EDGES) atomicAdd(&g_deg[ei[N_EDGES + e]], 1);
}

__global__ void scan_kernel() {
    __shared__ int s[1024];
    int tid = threadIdx.x;
    const int per = (N_NODES + 1023) / 1024;
    int start = tid * per;
    int end = min(start + per, N_NODES);
    int sum = 0;
    for (int i = start; i < end; i++) sum += g_deg[i];
    s[tid] = sum;
    __syncthreads();
    #pragma unroll
    for (int off = 1; off < 1024; off <<= 1) {
        int v = (tid >= off) ? s[tid - off] : 0;
        __syncthreads();
        s[tid] += v;
        __syncthreads();
    }
    int run = (tid == 0) ? 0 : s[tid - 1];
    for (int i = start; i < end; i++) {
        g_rowptr[i] = run;
        g_wcur[i]   = run;
        run += g_deg[i];
    }
    if (tid == 0) g_rowptr[N_NODES] = s[1023];
}

__global__ void fill_kernel(const int* __restrict__ ei) {
    int e = blockIdx.x * blockDim.x + threadIdx.x;
    if (e < N_EDGES) {
        int d = ei[N_EDGES + e];
        int pos = atomicAdd(&g_wcur[d], 1);
        g_esrc[pos] = ei[e];
    }
}

// ---------------- aggregation: one warp per node (known-good) ----------------
__global__ void agg_kernel(const float4* __restrict__ x, float4* __restrict__ out) {
    int gw = (blockIdx.x * blockDim.x + threadIdx.x) >> 5;
    if (gw >= N_NODES) return;
    int lane = threadIdx.x & 31;
    float4 acc = x[(size_t)gw * 32 + lane];
    int beg = g_rowptr[gw];
    int end = g_rowptr[gw + 1];
    for (int e = beg; e < end; e++) {
        int s = g_esrc[e];
        float4 v = __ldg(&x[(size_t)s * 32 + lane]);
        acc.x += v.x; acc.y += v.y; acc.z += v.z; acc.w += v.w;
    }
    out[(size_t)gw * 32 + lane] = acc;
}

// ================= mma.sync tf32 fused MLP (R7 known-good) =================
// Warp partition: each of 8 warps = 2 m16-slabs x 8 n8-frags.
// B fragments reused across the 2 slabs -> LDS/warp/kstep: 36 -> 24.
#define W_STRIDE 132
#define SM_H   0
#define SM_W1  (128 * W_STRIDE * 4)
#define SM_W2  (2 * 128 * W_STRIDE * 4)
#define SM_B   (3 * 128 * W_STRIDE * 4)
#define MLP_SMEM (SM_B + 1024)

__device__ __forceinline__ uint32_t f2tf32(float f) {
    uint32_t r;
    asm("cvt.rna.tf32.f32 %0, %1;" : "=r"(r) : "f"(f));
    return r;
}

__device__ __forceinline__ void mma16n8k8(float* c,
                                          uint32_t a0, uint32_t a1, uint32_t a2, uint32_t a3,
                                          uint32_t b0, uint32_t b1) {
    asm volatile(
        "mma.sync.aligned.m16n8k8.row.col.f32.tf32.tf32.f32 "
        "{%0,%1,%2,%3}, {%4,%5,%6,%7}, {%8,%9}, {%0,%1,%2,%3};"
        : "+f"(c[0]), "+f"(c[1]), "+f"(c[2]), "+f"(c[3])
        : "r"(a0), "r"(a1), "r"(a2), "r"(a3), "r"(b0), "r"(b1));
}

__global__ void __launch_bounds__(256, 1)
mlp_mma(const float* __restrict__ h,
        const float* __restrict__ W1, const float* __restrict__ b1,
        const float* __restrict__ W2, const float* __restrict__ b2,
        float* __restrict__ out, int relu_out)
{
    extern __shared__ __align__(16) char sm[];
    float*    sH  = (float*)(sm + SM_H);
    uint32_t* sW1 = (uint32_t*)(sm + SM_W1);
    uint32_t* sW2 = (uint32_t*)(sm + SM_W2);
    float*    sB1 = (float*)(sm + SM_B);
    float*    sB2 = sB1 + 128;

    const int tid  = threadIdx.x;
    const int wid  = tid >> 5;
    const int lane = tid & 31;
    const int gid  = lane >> 2;   // 0..7
    const int tig  = lane & 3;    // 0..3
    const int fh   = wid & 1;     // n half: fh*64
    const int sp   = wid >> 1;    // slab pair: rows sp*32 .. sp*32+31
    const int nbase = fh * 64;
    const int mbase = sp * 32;

    for (int i = tid; i < 16384; i += 256) {
        int k = i >> 7, n = i & 127;
        sW1[k * W_STRIDE + n] = f2tf32(W1[i]);
        sW2[k * W_STRIDE + n] = f2tf32(W2[i]);
    }
    if (tid < 128) { sB1[tid] = b1[tid]; sB2[tid] = b2[tid]; }
    __syncthreads();

    const int ntiles = (N_NODES + 127) / 128;
    const float* arow0 = sH + (mbase + gid) * W_STRIDE;
    const float* arow1 = arow0 + 16 * W_STRIDE;

    for (int t = blockIdx.x; t < ntiles; t += gridDim.x) {
        const int row0 = t * 128;

        // ---- stage tile block-wide (fp32, zero-padded) ----
        for (int i = tid; i < 128 * 32; i += 256) {
            int r = i >> 5, c4 = i & 31;
            int gr = row0 + r;
            float4 v = (gr < N_NODES) ? *(const float4*)(h + (size_t)gr * DIM + c4 * 4)
                                      : make_float4(0.f, 0.f, 0.f, 0.f);
            *(float4*)(sH + r * W_STRIDE + c4 * 4) = v;
        }
        __syncthreads();

        float acc[2][8][4];
        #pragma unroll
        for (int s = 0; s < 2; s++)
            #pragma unroll
            for (int f = 0; f < 8; f++)
                acc[s][f][0] = acc[s][f][1] = acc[s][f][2] = acc[s][f][3] = 0.f;

        // ---- GEMM1 ----
        #pragma unroll 2
        for (int ks = 0; ks < 16; ks++) {
            const int k0 = ks * 8;
            uint32_t a00 = f2tf32(arow0[k0 + tig]);
            uint32_t a01 = f2tf32(arow0[8 * W_STRIDE + k0 + tig]);
            uint32_t a02 = f2tf32(arow0[k0 + tig + 4]);
            uint32_t a03 = f2tf32(arow0[8 * W_STRIDE + k0 + tig + 4]);
            uint32_t a10 = f2tf32(arow1[k0 + tig]);
            uint32_t a11 = f2tf32(arow1[8 * W_STRIDE + k0 + tig]);
            uint32_t a12 = f2tf32(arow1[k0 + tig + 4]);
            uint32_t a13 = f2tf32(arow1[8 * W_STRIDE + k0 + tig + 4]);
            const uint32_t* bk0 = sW1 + (k0 + tig) * W_STRIDE + nbase + gid;
            const uint32_t* bk1 = bk0 + 4 * W_STRIDE;
            #pragma unroll
            for (int f = 0; f < 8; f++) {
                uint32_t b0 = bk0[f * 8], b1 = bk1[f * 8];
                mma16n8k8(acc[0][f], a00, a01, a02, a03, b0, b1);
                mma16n8k8(acc[1][f], a10, a11, a12, a13, b0, b1);
            }
        }

        // ---- epilogue1: relu(acc + b1) -> sH ----
        __syncthreads();
        #pragma unroll
        for (int s = 0; s < 2; s++) {
            int ra = mbase + s * 16 + gid;
            #pragma unroll
            for (int f = 0; f < 8; f++) {
                int col = nbase + 8 * f + 2 * tig;
                float v0 = fmaxf(acc[s][f][0] + sB1[col],     0.f);
                float v1 = fmaxf(acc[s][f][1] + sB1[col + 1], 0.f);
                float v2 = fmaxf(acc[s][f][2] + sB1[col],     0.f);
                float v3 = fmaxf(acc[s][f][3] + sB1[col + 1], 0.f);
                *(float2*)(sH + ra * W_STRIDE + col)       = make_float2(v0, v1);
                *(float2*)(sH + (ra + 8) * W_STRIDE + col) = make_float2(v2, v3);
            }
        }
        __syncthreads();

        #pragma unroll
        for (int s = 0; s < 2; s++)
            #pragma unroll
            for (int f = 0; f < 8; f++)
                acc[s][f][0] = acc[s][f][1] = acc[s][f][2] = acc[s][f][3] = 0.f;

        // ---- GEMM2 ----
        #pragma unroll 2
        for (int ks = 0; ks < 16; ks++) {
            const int k0 = ks * 8;
            uint32_t a00 = f2tf32(arow0[k0 + tig]);
            uint32_t a01 = f2tf32(arow0[8 * W_STRIDE + k0 + tig]);
            uint32_t a02 = f2tf32(arow0[k0 + tig + 4]);
            uint32_t a03 = f2tf32(arow0[8 * W_STRIDE + k0 + tig + 4]);
            uint32_t a10 = f2tf32(arow1[k0 + tig]);
            uint32_t a11 = f2tf32(arow1[8 * W_STRIDE + k0 + tig]);
            uint32_t a12 = f2tf32(arow1[k0 + tig + 4]);
            uint32_t a13 = f2tf32(arow1[8 * W_STRIDE + k0 + tig + 4]);
            const uint32_t* bk0 = sW2 + (k0 + tig) * W_STRIDE + nbase + gid;
            const uint32_t* bk1 = bk0 + 4 * W_STRIDE;
            #pragma unroll
            for (int f = 0; f < 8; f++) {
                uint32_t b0 = bk0[f * 8], b1 = bk1[f * 8];
                mma16n8k8(acc[0][f], a00, a01, a02, a03, b0, b1);
                mma16n8k8(acc[1][f], a10, a11, a12, a13, b0, b1);
            }
        }

        // ---- epilogue2: acc + b2 (+relu) -> gmem ----
        #pragma unroll
        for (int s = 0; s < 2; s++) {
            const int gr0 = row0 + mbase + s * 16 + gid;
            const int gr1 = gr0 + 8;
            #pragma unroll
            for (int f = 0; f < 8; f++) {
                int col = nbase + 8 * f + 2 * tig;
                if (gr0 < N_NODES) {
                    float v0 = acc[s][f][0] + sB2[col];
                    float v1 = acc[s][f][1] + sB2[col + 1];
                    if (relu_out) { v0 = fmaxf(v0, 0.f); v1 = fmaxf(v1, 0.f); }
                    *(float2*)(out + (size_t)gr0 * DIM + col) = make_float2(v0, v1);
                }
                if (gr1 < N_NODES) {
                    float v2 = acc[s][f][2] + sB2[col];
                    float v3 = acc[s][f][3] + sB2[col + 1];
                    if (relu_out) { v2 = fmaxf(v2, 0.f); v3 = fmaxf(v3, 0.f); }
                    *(float2*)(out + (size_t)gr1 * DIM + col) = make_float2(v2, v3);
                }
            }
        }
        __syncthreads();
    }
}

// ---------------- launch ----------------
extern "C" void kernel_launch(void* const* d_in, const int* in_sizes, int n_in,
                              void* d_out, int out_size)
{
    const float* x  = (const float*)d_in[0];
    const int*   ei = (const int*)d_in[1];
    const float* W1 = (const float*)d_in[2];
    const float* b1 = (const float*)d_in[3];
    const float* W2 = (const float*)d_in[4];
    const float* b2 = (const float*)d_in[5];
    float* out = (float*)d_out;

    static float* bufA = nullptr;
    static float* bufB = nullptr;
    static int*   degp = nullptr;
    if (!bufA) {
        void *pA, *pB, *pD;
        cudaGetSymbolAddress(&pA, g_bufA);
        cudaGetSymbolAddress(&pB, g_bufB);
        cudaGetSymbolAddress(&pD, g_deg);
        bufA = (float*)pA;
        bufB = (float*)pB;
        degp = (int*)pD;
        cudaFuncSetAttribute(mlp_mma, cudaFuncAttributeMaxDynamicSharedMemorySize, MLP_SMEM);
    }

    // CSR build (memset replaces zero kernel; capture-legal async)
    cudaMemsetAsync(degp, 0, N_NODES * sizeof(int), 0);
    count_kernel<<<(N_EDGES + 255) / 256, 256>>>(ei);
    scan_kernel<<<1, 1024>>>();
    fill_kernel<<<(N_EDGES + 255) / 256, 256>>>(ei);

    const int agg_grid = (N_NODES * 32 + 255) / 256;

    // layer 0
    agg_kernel<<<agg_grid, 256>>>((const float4*)x, (float4*)bufB);
    mlp_mma<<<148, 256, MLP_SMEM>>>(bufB, W1, b1, W2, b2, bufA, 1);
    // layer 1
    agg_kernel<<<agg_grid, 256>>>((const float4*)bufA, (float4*)bufB);
    mlp_mma<<<148, 256, MLP_SMEM>>>(bufB, W1 + 16384, b1 + 128, W2 + 16384, b2 + 128, bufA, 1);
    // layer 2
    agg_kernel<<<agg_grid, 256>>>((const float4*)bufA, (float4*)bufB);
    mlp_mma<<<148, 256, MLP_SMEM>>>(bufB, W1 + 32768, b1 + 256, W2 + 32768, b2 + 256, out, 0);
}

// round 11
// speedup vs baseline: 2.2488x; 1.2288x over previous
#include <cuda_runtime.h>
#include <cuda_fp16.h>
#include <cstdint>

#define N_NODES 100000
#define N_EDGES 1600000
#define DIM     128

// ---------------- scratch (no allocations allowed) ----------------
__device__ int g_deg[N_NODES];
__device__ int g_rowptr[N_NODES + 1];
__device__ int g_wcur[N_NODES];
__device__ int g_esrc[N_EDGES];
__device__ __align__(16) float g_bufA[(size_t)N_NODES * DIM];
__device__ __align__(16) float g_bufB[(size_t)N_NODES * DIM];

// ---------------- CSR build ----------------
__global__ void count_kernel(const int* __restrict__ ei) {
    int e = blockIdx.x * blockDim.x + threadIdx.x;
    if (e < N_EDGES) atomicAdd(&g_deg[ei[N_EDGES + e]], 1);
}

__global__ void scan_kernel() {
    __shared__ int s[1024];
    int tid = threadIdx.x;
    const int per = (N_NODES + 1023) / 1024;
    int start = tid * per;
    int end = min(start + per, N_NODES);
    int sum = 0;
    for (int i = start; i < end; i++) sum += g_deg[i];
    s[tid] = sum;
    __syncthreads();
    #pragma unroll
    for (int off = 1; off < 1024; off <<= 1) {
        int v = (tid >= off) ? s[tid - off] : 0;
        __syncthreads();
        s[tid] += v;
        __syncthreads();
    }
    int run = (tid == 0) ? 0 : s[tid - 1];
    for (int i = start; i < end; i++) {
        g_rowptr[i] = run;
        g_wcur[i]   = run;
        run += g_deg[i];
    }
    if (tid == 0) g_rowptr[N_NODES] = s[1023];
}

__global__ void fill_kernel(const int* __restrict__ ei) {
    int e = blockIdx.x * blockDim.x + threadIdx.x;
    if (e < N_EDGES) {
        int d = ei[N_EDGES + e];
        int pos = atomicAdd(&g_wcur[d], 1);
        g_esrc[pos] = ei[e];
    }
}

// ---------------- aggregation: one warp per node (known-good) ----------------
__global__ void agg_kernel(const float4* __restrict__ x, float4* __restrict__ out) {
    int gw = (blockIdx.x * blockDim.x + threadIdx.x) >> 5;
    if (gw >= N_NODES) return;
    int lane = threadIdx.x & 31;
    float4 acc = x[(size_t)gw * 32 + lane];
    int beg = g_rowptr[gw];
    int end = g_rowptr[gw + 1];
    for (int e = beg; e < end; e++) {
        int s = g_esrc[e];
        float4 v = __ldg(&x[(size_t)s * 32 + lane]);
        acc.x += v.x; acc.y += v.y; acc.z += v.z; acc.w += v.w;
    }
    out[(size_t)gw * 32 + lane] = acc;
}

// ================= fp16 mma.sync (m16n8k16) fused MLP =================
// Half-precision operands (same 10-bit mantissa as tf32), fp32 accumulate.
// smem ~103KB -> 2 CTAs/SM (16 warps). Warp partition: 2 m16-slabs x 8 n8-frags.
// Layouts (halves, stride 136): sH[row][k], sW[n][k] (pre-transposed for col-major B).
#define HSTRIDE 136
#define SM_H   0
#define SM_W1  (128 * HSTRIDE * 2)
#define SM_W2  (2 * 128 * HSTRIDE * 2)
#define SM_B   (3 * 128 * HSTRIDE * 2)
#define MLP_SMEM (SM_B + 1024)

__device__ __forceinline__ uint32_t h2u(__half2 h) {
    uint32_t u;
    memcpy(&u, &h, 4);
    return u;
}

__device__ __forceinline__ void mma16n8k16(float* c,
                                           uint32_t a0, uint32_t a1, uint32_t a2, uint32_t a3,
                                           uint32_t b0, uint32_t b1) {
    asm volatile(
        "mma.sync.aligned.m16n8k16.row.col.f32.f16.f16.f32 "
        "{%0,%1,%2,%3}, {%4,%5,%6,%7}, {%8,%9}, {%0,%1,%2,%3};"
        : "+f"(c[0]), "+f"(c[1]), "+f"(c[2]), "+f"(c[3])
        : "r"(a0), "r"(a1), "r"(a2), "r"(a3), "r"(b0), "r"(b1));
}

__global__ void __launch_bounds__(256, 2)
mlp_mma(const float* __restrict__ h,
        const float* __restrict__ W1, const float* __restrict__ b1,
        const float* __restrict__ W2, const float* __restrict__ b2,
        float* __restrict__ out, int relu_out)
{
    extern __shared__ __align__(16) char sm[];
    __half* sH  = (__half*)(sm + SM_H);
    __half* sW1 = (__half*)(sm + SM_W1);
    __half* sW2 = (__half*)(sm + SM_W2);
    float*  sB1 = (float*)(sm + SM_B);
    float*  sB2 = sB1 + 128;

    const int tid  = threadIdx.x;
    const int wid  = tid >> 5;
    const int lane = tid & 31;
    const int gid  = lane >> 2;   // 0..7
    const int tig  = lane & 3;    // 0..3
    const int fh   = wid & 1;     // n half: fh*64
    const int sp   = wid >> 1;    // slab pair: rows sp*32 .. sp*32+31
    const int nbase = fh * 64;
    const int mbase = sp * 32;

    // stage weights transposed to [n][k] halves (B col-major frags read k-pairs)
    for (int i = tid; i < 8192; i += 256) {
        int k = (i >> 7) * 2, n = i & 127;
        float w1a = W1[k * 128 + n],  w1b = W1[(k + 1) * 128 + n];
        float w2a = W2[k * 128 + n],  w2b = W2[(k + 1) * 128 + n];
        *(uint32_t*)(sW1 + n * HSTRIDE + k) = h2u(__floats2half2_rn(w1a, w1b));
        *(uint32_t*)(sW2 + n * HSTRIDE + k) = h2u(__floats2half2_rn(w2a, w2b));
    }
    if (tid < 128) { sB1[tid] = b1[tid]; sB2[tid] = b2[tid]; }
    __syncthreads();

    const int ntiles = (N_NODES + 127) / 128;
    const __half* arow0 = sH + (mbase + gid) * HSTRIDE;
    const __half* arow1 = arow0 + 16 * HSTRIDE;

    for (int t = blockIdx.x; t < ntiles; t += gridDim.x) {
        const int row0 = t * 128;

        // ---- stage tile block-wide (fp16, zero-padded) ----
        for (int i = tid; i < 128 * 32; i += 256) {
            int r = i >> 5, c4 = i & 31;
            int gr = row0 + r;
            float4 v = (gr < N_NODES) ? *(const float4*)(h + (size_t)gr * DIM + c4 * 4)
                                      : make_float4(0.f, 0.f, 0.f, 0.f);
            uint2 p;
            p.x = h2u(__floats2half2_rn(v.x, v.y));
            p.y = h2u(__floats2half2_rn(v.z, v.w));
            *(uint2*)(sH + r * HSTRIDE + c4 * 4) = p;
        }
        __syncthreads();

        float acc[2][8][4];
        #pragma unroll
        for (int s = 0; s < 2; s++)
            #pragma unroll
            for (int f = 0; f < 8; f++)
                acc[s][f][0] = acc[s][f][1] = acc[s][f][2] = acc[s][f][3] = 0.f;

        // ---- GEMM1 (8 k16-steps) ----
        #pragma unroll
        for (int ks = 0; ks < 8; ks++) {
            const int k0 = ks * 16;
            uint32_t a00 = *(const uint32_t*)(arow0 + k0 + 2 * tig);
            uint32_t a01 = *(const uint32_t*)(arow0 + 8 * HSTRIDE + k0 + 2 * tig);
            uint32_t a02 = *(const uint32_t*)(arow0 + k0 + 2 * tig + 8);
            uint32_t a03 = *(const uint32_t*)(arow0 + 8 * HSTRIDE + k0 + 2 * tig + 8);
            uint32_t a10 = *(const uint32_t*)(arow1 + k0 + 2 * tig);
            uint32_t a11 = *(const uint32_t*)(arow1 + 8 * HSTRIDE + k0 + 2 * tig);
            uint32_t a12 = *(const uint32_t*)(arow1 + k0 + 2 * tig + 8);
            uint32_t a13 = *(const uint32_t*)(arow1 + 8 * HSTRIDE + k0 + 2 * tig + 8);
            const __half* bp = sW1 + (nbase + gid) * HSTRIDE + k0 + 2 * tig;
            #pragma unroll
            for (int f = 0; f < 8; f++) {
                uint32_t b0 = *(const uint32_t*)(bp + f * 8 * HSTRIDE);
                uint32_t b1 = *(const uint32_t*)(bp + f * 8 * HSTRIDE + 8);
                mma16n8k16(acc[0][f], a00, a01, a02, a03, b0, b1);
                mma16n8k16(acc[1][f], a10, a11, a12, a13, b0, b1);
            }
        }

        // ---- epilogue1: relu(acc + b1) -> sH (fp16) ----
        __syncthreads();
        #pragma unroll
        for (int s = 0; s < 2; s++) {
            int ra = mbase + s * 16 + gid;
            #pragma unroll
            for (int f = 0; f < 8; f++) {
                int col = nbase + 8 * f + 2 * tig;
                float v0 = fmaxf(acc[s][f][0] + sB1[col],     0.f);
                float v1 = fmaxf(acc[s][f][1] + sB1[col + 1], 0.f);
                float v2 = fmaxf(acc[s][f][2] + sB1[col],     0.f);
                float v3 = fmaxf(acc[s][f][3] + sB1[col + 1], 0.f);
                *(uint32_t*)(sH + ra * HSTRIDE + col)       = h2u(__floats2half2_rn(v0, v1));
                *(uint32_t*)(sH + (ra + 8) * HSTRIDE + col) = h2u(__floats2half2_rn(v2, v3));
            }
        }
        __syncthreads();

        #pragma unroll
        for (int s = 0; s < 2; s++)
            #pragma unroll
            for (int f = 0; f < 8; f++)
                acc[s][f][0] = acc[s][f][1] = acc[s][f][2] = acc[s][f][3] = 0.f;

        // ---- GEMM2 ----
        #pragma unroll
        for (int ks = 0; ks < 8; ks++) {
            const int k0 = ks * 16;
            uint32_t a00 = *(const uint32_t*)(arow0 + k0 + 2 * tig);
            uint32_t a01 = *(const uint32_t*)(arow0 + 8 * HSTRIDE + k0 + 2 * tig);
            uint32_t a02 = *(const uint32_t*)(arow0 + k0 + 2 * tig + 8);
            uint32_t a03 = *(const uint32_t*)(arow0 + 8 * HSTRIDE + k0 + 2 * tig + 8);
            uint32_t a10 = *(const uint32_t*)(arow1 + k0 + 2 * tig);
            uint32_t a11 = *(const uint32_t*)(arow1 + 8 * HSTRIDE + k0 + 2 * tig);
            uint32_t a12 = *(const uint32_t*)(arow1 + k0 + 2 * tig + 8);
            uint32_t a13 = *(const uint32_t*)(arow1 + 8 * HSTRIDE + k0 + 2 * tig + 8);
            const __half* bp = sW2 + (nbase + gid) * HSTRIDE + k0 + 2 * tig;
            #pragma unroll
            for (int f = 0; f < 8; f++) {
                uint32_t b0 = *(const uint32_t*)(bp + f * 8 * HSTRIDE);
                uint32_t b1 = *(const uint32_t*)(bp + f * 8 * HSTRIDE + 8);
                mma16n8k16(acc[0][f], a00, a01, a02, a03, b0, b1);
                mma16n8k16(acc[1][f], a10, a11, a12, a13, b0, b1);
            }
        }

        // ---- epilogue2: acc + b2 (+relu) -> gmem (fp32) ----
        #pragma unroll
        for (int s = 0; s < 2; s++) {
            const int gr0 = row0 + mbase + s * 16 + gid;
            const int gr1 = gr0 + 8;
            #pragma unroll
            for (int f = 0; f < 8; f++) {
                int col = nbase + 8 * f + 2 * tig;
                if (gr0 < N_NODES) {
                    float v0 = acc[s][f][0] + sB2[col];
                    float v1 = acc[s][f][1] + sB2[col + 1];
                    if (relu_out) { v0 = fmaxf(v0, 0.f); v1 = fmaxf(v1, 0.f); }
                    *(float2*)(out + (size_t)gr0 * DIM + col) = make_float2(v0, v1);
                }
                if (gr1 < N_NODES) {
                    float v2 = acc[s][f][2] + sB2[col];
                    float v3 = acc[s][f][3] + sB2[col + 1];
                    if (relu_out) { v2 = fmaxf(v2, 0.f); v3 = fmaxf(v3, 0.f); }
                    *(float2*)(out + (size_t)gr1 * DIM + col) = make_float2(v2, v3);
                }
            }
        }
        __syncthreads();
    }
}

// ---------------- launch ----------------
extern "C" void kernel_launch(void* const* d_in, const int* in_sizes, int n_in,
                              void* d_out, int out_size)
{
    const float* x  = (const float*)d_in[0];
    const int*   ei = (const int*)d_in[1];
    const float* W1 = (const float*)d_in[2];
    const float* b1 = (const float*)d_in[3];
    const float* W2 = (const float*)d_in[4];
    const float* b2 = (const float*)d_in[5];
    float* out = (float*)d_out;

    static float* bufA = nullptr;
    static float* bufB = nullptr;
    static int*   degp = nullptr;
    if (!bufA) {
        void *pA, *pB, *pD;
        cudaGetSymbolAddress(&pA, g_bufA);
        cudaGetSymbolAddress(&pB, g_bufB);
        cudaGetSymbolAddress(&pD, g_deg);
        bufA = (float*)pA;
        bufB = (float*)pB;
        degp = (int*)pD;
        cudaFuncSetAttribute(mlp_mma, cudaFuncAttributeMaxDynamicSharedMemorySize, MLP_SMEM);
    }

    // CSR build
    cudaMemsetAsync(degp, 0, N_NODES * sizeof(int), 0);
    count_kernel<<<(N_EDGES + 255) / 256, 256>>>(ei);
    scan_kernel<<<1, 1024>>>();
    fill_kernel<<<(N_EDGES + 255) / 256, 256>>>(ei);

    const int agg_grid = (N_NODES * 32 + 255) / 256;
    const int mlp_grid = 296;   // 2 CTAs/SM x 148 SMs

    // layer 0
    agg_kernel<<<agg_grid, 256>>>((const float4*)x, (float4*)bufB);
    mlp_mma<<<mlp_grid, 256, MLP_SMEM>>>(bufB, W1, b1, W2, b2, bufA, 1);
    // layer 1
    agg_kernel<<<agg_grid, 256>>>((const float4*)bufA, (float4*)bufB);
    mlp_mma<<<mlp_grid, 256, MLP_SMEM>>>(bufB, W1 + 16384, b1 + 128, W2 + 16384, b2 + 128, bufA, 1);
    // layer 2
    agg_kernel<<<agg_grid, 256>>>((const float4*)bufA, (float4*)bufB);
    mlp_mma<<<mlp_grid, 256, MLP_SMEM>>>(bufB, W1 + 32768, b1 + 256, W2 + 32768, b2 + 256, out, 0);
}

// round 12
// speedup vs baseline: 2.4451x; 1.0873x over previous
#include <cuda_runtime.h>
#include <cuda_fp16.h>
#include <cstdint>

#define N_NODES 100000
#define N_EDGES 1600000
#define DIM     128

// ---------------- scratch (no allocations allowed) ----------------
__device__ int g_deg[N_NODES];
__device__ int g_rowptr[N_NODES + 1];
__device__ int g_wcur[N_NODES];
__device__ int g_esrc[N_EDGES];
__device__ __align__(16) float g_bufA[(size_t)N_NODES * DIM];
__device__ __align__(16) float g_bufB[(size_t)N_NODES * DIM];

// ---------------- CSR build ----------------
__global__ void count_kernel(const int* __restrict__ ei) {
    int e = blockIdx.x * blockDim.x + threadIdx.x;
    if (e < N_EDGES) atomicAdd(&g_deg[ei[N_EDGES + e]], 1);
}

__global__ void scan_kernel() {
    __shared__ int s[1024];
    int tid = threadIdx.x;
    const int per = (N_NODES + 1023) / 1024;
    int start = tid * per;
    int end = min(start + per, N_NODES);
    int sum = 0;
    for (int i = start; i < end; i++) sum += g_deg[i];
    s[tid] = sum;
    __syncthreads();
    #pragma unroll
    for (int off = 1; off < 1024; off <<= 1) {
        int v = (tid >= off) ? s[tid - off] : 0;
        __syncthreads();
        s[tid] += v;
        __syncthreads();
    }
    int run = (tid == 0) ? 0 : s[tid - 1];
    for (int i = start; i < end; i++) {
        g_rowptr[i] = run;
        g_wcur[i]   = run;
        run += g_deg[i];
    }
    if (tid == 0) g_rowptr[N_NODES] = s[1023];
}

__global__ void fill_kernel(const int* __restrict__ ei) {
    int e = blockIdx.x * blockDim.x + threadIdx.x;
    if (e < N_EDGES) {
        int d = ei[N_EDGES + e];
        int pos = atomicAdd(&g_wcur[d], 1);
        g_esrc[pos] = ei[e];
    }
}

__device__ __forceinline__ uint32_t h2u(__half2 h) {
    uint32_t u;
    memcpy(&u, &h, 4);
    return u;
}

// ---------------- aggregation fp32 (layer 0; known-good) ----------------
__global__ void agg_kernel(const float4* __restrict__ x, float4* __restrict__ out) {
    int gw = (blockIdx.x * blockDim.x + threadIdx.x) >> 5;
    if (gw >= N_NODES) return;
    int lane = threadIdx.x & 31;
    float4 acc = x[(size_t)gw * 32 + lane];
    int beg = g_rowptr[gw];
    int end = g_rowptr[gw + 1];
    for (int e = beg; e < end; e++) {
        int s = g_esrc[e];
        float4 v = __ldg(&x[(size_t)s * 32 + lane]);
        acc.x += v.x; acc.y += v.y; acc.z += v.z; acc.w += v.w;
    }
    out[(size_t)gw * 32 + lane] = acc;
}

// ---------------- aggregation fp16 in/out, fp32 accumulate (layers 1,2) ----------------
__global__ void agg_kernel_h(const uint2* __restrict__ x, uint2* __restrict__ out) {
    int gw = (blockIdx.x * blockDim.x + threadIdx.x) >> 5;
    if (gw >= N_NODES) return;
    int lane = threadIdx.x & 31;
    uint2 sv = __ldg(&x[(size_t)gw * 32 + lane]);
    __half2 h0, h1;
    memcpy(&h0, &sv.x, 4); memcpy(&h1, &sv.y, 4);
    float2 a0 = __half22float2(h0);
    float2 a1 = __half22float2(h1);
    int e = g_rowptr[gw];
    int end = g_rowptr[gw + 1];
    for (; e < end; e++) {
        int s = g_esrc[e];
        uint2 v = __ldg(&x[(size_t)s * 32 + lane]);
        __half2 v0, v1;
        memcpy(&v0, &v.x, 4); memcpy(&v1, &v.y, 4);
        float2 f0 = __half22float2(v0);
        float2 f1 = __half22float2(v1);
        a0.x += f0.x; a0.y += f0.y;
        a1.x += f1.x; a1.y += f1.y;
    }
    uint2 o;
    o.x = h2u(__floats2half2_rn(a0.x, a0.y));
    o.y = h2u(__floats2half2_rn(a1.x, a1.y));
    out[(size_t)gw * 32 + lane] = o;
}

// ================= fp16 mma.sync (m16n8k16) fused MLP =================
// 2 CTAs/SM. Warp partition: 2 m16-slabs x 8 n8-frags; B frags shared across slabs.
// IN_H: input rows already fp16 (raw copy); OUT_H: write fp16 output.
#define HSTRIDE 136
#define SM_H   0
#define SM_W1  (128 * HSTRIDE * 2)
#define SM_W2  (2 * 128 * HSTRIDE * 2)
#define SM_B   (3 * 128 * HSTRIDE * 2)
#define MLP_SMEM (SM_B + 1024)

__device__ __forceinline__ void mma16n8k16(float* c,
                                           uint32_t a0, uint32_t a1, uint32_t a2, uint32_t a3,
                                           uint32_t b0, uint32_t b1) {
    asm volatile(
        "mma.sync.aligned.m16n8k16.row.col.f32.f16.f16.f32 "
        "{%0,%1,%2,%3}, {%4,%5,%6,%7}, {%8,%9}, {%0,%1,%2,%3};"
        : "+f"(c[0]), "+f"(c[1]), "+f"(c[2]), "+f"(c[3])
        : "r"(a0), "r"(a1), "r"(a2), "r"(a3), "r"(b0), "r"(b1));
}

template<bool IN_H, bool OUT_H>
__global__ void __launch_bounds__(256, 2)
mlp_mma(const void* __restrict__ hin,
        const float* __restrict__ W1, const float* __restrict__ b1,
        const float* __restrict__ W2, const float* __restrict__ b2,
        void* __restrict__ outv, int relu_out)
{
    extern __shared__ __align__(16) char sm[];
    __half* sH  = (__half*)(sm + SM_H);
    __half* sW1 = (__half*)(sm + SM_W1);
    __half* sW2 = (__half*)(sm + SM_W2);
    float*  sB1 = (float*)(sm + SM_B);
    float*  sB2 = sB1 + 128;

    const int tid  = threadIdx.x;
    const int wid  = tid >> 5;
    const int lane = tid & 31;
    const int gid  = lane >> 2;   // 0..7
    const int tig  = lane & 3;    // 0..3
    const int fh   = wid & 1;
    const int sp   = wid >> 1;
    const int nbase = fh * 64;
    const int mbase = sp * 32;

    for (int i = tid; i < 8192; i += 256) {
        int k = (i >> 7) * 2, n = i & 127;
        float w1a = W1[k * 128 + n],  w1b = W1[(k + 1) * 128 + n];
        float w2a = W2[k * 128 + n],  w2b = W2[(k + 1) * 128 + n];
        *(uint32_t*)(sW1 + n * HSTRIDE + k) = h2u(__floats2half2_rn(w1a, w1b));
        *(uint32_t*)(sW2 + n * HSTRIDE + k) = h2u(__floats2half2_rn(w2a, w2b));
    }
    if (tid < 128) { sB1[tid] = b1[tid]; sB2[tid] = b2[tid]; }
    __syncthreads();

    const int ntiles = (N_NODES + 127) / 128;
    const __half* arow0 = sH + (mbase + gid) * HSTRIDE;
    const __half* arow1 = arow0 + 16 * HSTRIDE;

    for (int t = blockIdx.x; t < ntiles; t += gridDim.x) {
        const int row0 = t * 128;

        // ---- stage tile block-wide ----
        for (int i = tid; i < 128 * 32; i += 256) {
            int r = i >> 5, c4 = i & 31;
            int gr = row0 + r;
            uint2 p = make_uint2(0u, 0u);
            if (IN_H) {
                if (gr < N_NODES)
                    p = __ldg(&((const uint2*)hin)[(size_t)gr * 32 + c4]);
            } else {
                if (gr < N_NODES) {
                    float4 v = *(const float4*)((const float*)hin + (size_t)gr * DIM + c4 * 4);
                    p.x = h2u(__floats2half2_rn(v.x, v.y));
                    p.y = h2u(__floats2half2_rn(v.z, v.w));
                }
            }
            *(uint2*)(sH + r * HSTRIDE + c4 * 4) = p;
        }
        __syncthreads();

        float acc[2][8][4];
        #pragma unroll
        for (int s = 0; s < 2; s++)
            #pragma unroll
            for (int f = 0; f < 8; f++)
                acc[s][f][0] = acc[s][f][1] = acc[s][f][2] = acc[s][f][3] = 0.f;

        // ---- GEMM1 ----
        #pragma unroll
        for (int ks = 0; ks < 8; ks++) {
            const int k0 = ks * 16;
            uint32_t a00 = *(const uint32_t*)(arow0 + k0 + 2 * tig);
            uint32_t a01 = *(const uint32_t*)(arow0 + 8 * HSTRIDE + k0 + 2 * tig);
            uint32_t a02 = *(const uint32_t*)(arow0 + k0 + 2 * tig + 8);
            uint32_t a03 = *(const uint32_t*)(arow0 + 8 * HSTRIDE + k0 + 2 * tig + 8);
            uint32_t a10 = *(const uint32_t*)(arow1 + k0 + 2 * tig);
            uint32_t a11 = *(const uint32_t*)(arow1 + 8 * HSTRIDE + k0 + 2 * tig);
            uint32_t a12 = *(const uint32_t*)(arow1 + k0 + 2 * tig + 8);
            uint32_t a13 = *(const uint32_t*)(arow1 + 8 * HSTRIDE + k0 + 2 * tig + 8);
            const __half* bp = sW1 + (nbase + gid) * HSTRIDE + k0 + 2 * tig;
            #pragma unroll
            for (int f = 0; f < 8; f++) {
                uint32_t b0 = *(const uint32_t*)(bp + f * 8 * HSTRIDE);
                uint32_t b1 = *(const uint32_t*)(bp + f * 8 * HSTRIDE + 8);
                mma16n8k16(acc[0][f], a00, a01, a02, a03, b0, b1);
                mma16n8k16(acc[1][f], a10, a11, a12, a13, b0, b1);
            }
        }

        // ---- epilogue1: relu(acc + b1) -> sH (fp16) ----
        __syncthreads();
        #pragma unroll
        for (int s = 0; s < 2; s++) {
            int ra = mbase + s * 16 + gid;
            #pragma unroll
            for (int f = 0; f < 8; f++) {
                int col = nbase + 8 * f + 2 * tig;
                float v0 = fmaxf(acc[s][f][0] + sB1[col],     0.f);
                float v1 = fmaxf(acc[s][f][1] + sB1[col + 1], 0.f);
                float v2 = fmaxf(acc[s][f][2] + sB1[col],     0.f);
                float v3 = fmaxf(acc[s][f][3] + sB1[col + 1], 0.f);
                *(uint32_t*)(sH + ra * HSTRIDE + col)       = h2u(__floats2half2_rn(v0, v1));
                *(uint32_t*)(sH + (ra + 8) * HSTRIDE + col) = h2u(__floats2half2_rn(v2, v3));
            }
        }
        __syncthreads();

        #pragma unroll
        for (int s = 0; s < 2; s++)
            #pragma unroll
            for (int f = 0; f < 8; f++)
                acc[s][f][0] = acc[s][f][1] = acc[s][f][2] = acc[s][f][3] = 0.f;

        // ---- GEMM2 ----
        #pragma unroll
        for (int ks = 0; ks < 8; ks++) {
            const int k0 = ks * 16;
            uint32_t a00 = *(const uint32_t*)(arow0 + k0 + 2 * tig);
            uint32_t a01 = *(const uint32_t*)(arow0 + 8 * HSTRIDE + k0 + 2 * tig);
            uint32_t a02 = *(const uint32_t*)(arow0 + k0 + 2 * tig + 8);
            uint32_t a03 = *(const uint32_t*)(arow0 + 8 * HSTRIDE + k0 + 2 * tig + 8);
            uint32_t a10 = *(const uint32_t*)(arow1 + k0 + 2 * tig);
            uint32_t a11 = *(const uint32_t*)(arow1 + 8 * HSTRIDE + k0 + 2 * tig);
            uint32_t a12 = *(const uint32_t*)(arow1 + k0 + 2 * tig + 8);
            uint32_t a13 = *(const uint32_t*)(arow1 + 8 * HSTRIDE + k0 + 2 * tig + 8);
            const __half* bp = sW2 + (nbase + gid) * HSTRIDE + k0 + 2 * tig;
            #pragma unroll
            for (int f = 0; f < 8; f++) {
                uint32_t b0 = *(const uint32_t*)(bp + f * 8 * HSTRIDE);
                uint32_t b1 = *(const uint32_t*)(bp + f * 8 * HSTRIDE + 8);
                mma16n8k16(acc[0][f], a00, a01, a02, a03, b0, b1);
                mma16n8k16(acc[1][f], a10, a11, a12, a13, b0, b1);
            }
        }

        // ---- epilogue2: acc + b2 (+relu) -> gmem ----
        #pragma unroll
        for (int s = 0; s < 2; s++) {
            const int gr0 = row0 + mbase + s * 16 + gid;
            const int gr1 = gr0 + 8;
            #pragma unroll
            for (int f = 0; f < 8; f++) {
                int col = nbase + 8 * f + 2 * tig;
                if (gr0 < N_NODES) {
                    float v0 = acc[s][f][0] + sB2[col];
                    float v1 = acc[s][f][1] + sB2[col + 1];
                    if (relu_out) { v0 = fmaxf(v0, 0.f); v1 = fmaxf(v1, 0.f); }
                    if (OUT_H) {
                        *(uint32_t*)((__half*)outv + (size_t)gr0 * DIM + col) =
                            h2u(__floats2half2_rn(v0, v1));
                    } else {
                        *(float2*)((float*)outv + (size_t)gr0 * DIM + col) = make_float2(v0, v1);
                    }
                }
                if (gr1 < N_NODES) {
                    float v2 = acc[s][f][2] + sB2[col];
                    float v3 = acc[s][f][3] + sB2[col + 1];
                    if (relu_out) { v2 = fmaxf(v2, 0.f); v3 = fmaxf(v3, 0.f); }
                    if (OUT_H) {
                        *(uint32_t*)((__half*)outv + (size_t)gr1 * DIM + col) =
                            h2u(__floats2half2_rn(v2, v3));
                    } else {
                        *(float2*)((float*)outv + (size_t)gr1 * DIM + col) = make_float2(v2, v3);
                    }
                }
            }
        }
        __syncthreads();
    }
}

// ---------------- launch ----------------
extern "C" void kernel_launch(void* const* d_in, const int* in_sizes, int n_in,
                              void* d_out, int out_size)
{
    const float* x  = (const float*)d_in[0];
    const int*   ei = (const int*)d_in[1];
    const float* W1 = (const float*)d_in[2];
    const float* b1 = (const float*)d_in[3];
    const float* W2 = (const float*)d_in[4];
    const float* b2 = (const float*)d_in[5];
    float* out = (float*)d_out;

    static float* bufA = nullptr;
    static float* bufB = nullptr;
    static int*   degp = nullptr;
    if (!bufA) {
        void *pA, *pB, *pD;
        cudaGetSymbolAddress(&pA, g_bufA);
        cudaGetSymbolAddress(&pB, g_bufB);
        cudaGetSymbolAddress(&pD, g_deg);
        bufA = (float*)pA;
        bufB = (float*)pB;
        degp = (int*)pD;
        cudaFuncSetAttribute(mlp_mma<false, true>,
                             cudaFuncAttributeMaxDynamicSharedMemorySize, MLP_SMEM);
        cudaFuncSetAttribute(mlp_mma<true, true>,
                             cudaFuncAttributeMaxDynamicSharedMemorySize, MLP_SMEM);
        cudaFuncSetAttribute(mlp_mma<true, false>,
                             cudaFuncAttributeMaxDynamicSharedMemorySize, MLP_SMEM);
    }

    // CSR build
    cudaMemsetAsync(degp, 0, N_NODES * sizeof(int), 0);
    count_kernel<<<(N_EDGES + 255) / 256, 256>>>(ei);
    scan_kernel<<<1, 1024>>>();
    fill_kernel<<<(N_EDGES + 255) / 256, 256>>>(ei);

    const int agg_grid = (N_NODES * 32 + 255) / 256;
    const int mlp_grid = 296;   // 2 CTAs/SM x 148 SMs

    // layer 0: fp32 in, fp16 out
    agg_kernel<<<agg_grid, 256>>>((const float4*)x, (float4*)bufB);
    mlp_mma<false, true><<<mlp_grid, 256, MLP_SMEM>>>(bufB, W1, b1, W2, b2, bufA, 1);
    // layer 1: fp16 throughout
    agg_kernel_h<<<agg_grid, 256>>>((const uint2*)bufA, (uint2*)bufB);
    mlp_mma<true, true><<<mlp_grid, 256, MLP_SMEM>>>(bufB, W1 + 16384, b1 + 128,
                                                     W2 + 16384, b2 + 128, bufA, 1);
    // layer 2: fp16 in, fp32 out
    agg_kernel_h<<<agg_grid, 256>>>((const uint2*)bufA, (uint2*)bufB);
    mlp_mma<true, false><<<mlp_grid, 256, MLP_SMEM>>>(bufB, W1 + 32768, b1 + 256,
                                                      W2 + 32768, b2 + 256, out, 0);
}

// round 13
// speedup vs baseline: 2.5140x; 1.0282x over previous
#include <cuda_runtime.h>
#include <cuda_fp16.h>
#include <cstdint>

#define N_NODES 100000
#define N_EDGES 1600000
#define DIM     128

// ---------------- scratch (no allocations allowed) ----------------
__device__ int g_deg[N_NODES];
__device__ int g_rowptr[N_NODES + 1];
__device__ int g_wcur[N_NODES];
__device__ int g_esrc[N_EDGES];
__device__ __align__(16) float g_bufA[(size_t)N_NODES * DIM];
__device__ __align__(16) float g_bufB[(size_t)N_NODES * DIM];

__device__ __forceinline__ uint32_t h2u(__half2 h) {
    uint32_t u;
    memcpy(&u, &h, 4);
    return u;
}

// ---------------- CSR build + x->fp16 convert (fused grid) ----------------
#define COUNT_BLOCKS 6250          // N_EDGES / 256
#define CONV_BLOCKS  12500         // N_NODES*32 / 256

__global__ void count_convert_kernel(const int* __restrict__ ei,
                                     const float4* __restrict__ x,
                                     uint2* __restrict__ x16) {
    if (blockIdx.x < COUNT_BLOCKS) {
        int e = blockIdx.x * blockDim.x + threadIdx.x;
        if (e < N_EDGES) atomicAdd(&g_deg[ei[N_EDGES + e]], 1);
    } else {
        int j = (blockIdx.x - COUNT_BLOCKS) * blockDim.x + threadIdx.x;
        if (j < N_NODES * 32) {
            float4 v = __ldg(&x[j]);
            uint2 p;
            p.x = h2u(__floats2half2_rn(v.x, v.y));
            p.y = h2u(__floats2half2_rn(v.z, v.w));
            x16[j] = p;
        }
    }
}

__global__ void scan_kernel() {
    __shared__ int wsum[32];
    int tid = threadIdx.x;                  // 1024 threads
    const int per = (N_NODES + 1023) / 1024;
    int start = tid * per;
    int end = min(start + per, N_NODES);
    int sum = 0;
    for (int i = start; i < end; i++) sum += g_deg[i];

    // warp-inclusive scan of per-thread sums
    int lane = tid & 31, warp = tid >> 5;
    int v = sum;
    #pragma unroll
    for (int off = 1; off < 32; off <<= 1) {
        int n = __shfl_up_sync(0xFFFFFFFFu, v, off);
        if (lane >= off) v += n;
    }
    if (lane == 31) wsum[warp] = v;
    __syncthreads();
    if (warp == 0) {
        int w = wsum[lane];
        #pragma unroll
        for (int off = 1; off < 32; off <<= 1) {
            int n = __shfl_up_sync(0xFFFFFFFFu, w, off);
            if (lane >= off) w += n;
        }
        wsum[lane] = w;
    }
    __syncthreads();

    int run = (warp > 0 ? wsum[warp - 1] : 0) + (v - sum);   // exclusive base
    for (int i = start; i < end; i++) {
        g_rowptr[i] = run;
        g_wcur[i]   = run;
        run += g_deg[i];
    }
    if (tid == 0) g_rowptr[N_NODES] = wsum[31];
}

__global__ void fill_kernel(const int* __restrict__ ei) {
    int e = blockIdx.x * blockDim.x + threadIdx.x;
    if (e < N_EDGES) {
        int d = ei[N_EDGES + e];
        int pos = atomicAdd(&g_wcur[d], 1);
        g_esrc[pos] = ei[e];
    }
}

// ---------------- aggregation: fp16 in/out, fp32 accumulate ----------------
__global__ void agg_kernel_h(const uint2* __restrict__ x, uint2* __restrict__ out) {
    int gw = (blockIdx.x * blockDim.x + threadIdx.x) >> 5;
    if (gw >= N_NODES) return;
    int lane = threadIdx.x & 31;
    uint2 sv = __ldg(&x[(size_t)gw * 32 + lane]);
    __half2 h0, h1;
    memcpy(&h0, &sv.x, 4); memcpy(&h1, &sv.y, 4);
    float2 a0 = __half22float2(h0);
    float2 a1 = __half22float2(h1);
    int e = g_rowptr[gw];
    int end = g_rowptr[gw + 1];
    for (; e < end; e++) {
        int s = g_esrc[e];
        uint2 v = __ldg(&x[(size_t)s * 32 + lane]);
        __half2 v0, v1;
        memcpy(&v0, &v.x, 4); memcpy(&v1, &v.y, 4);
        float2 f0 = __half22float2(v0);
        float2 f1 = __half22float2(v1);
        a0.x += f0.x; a0.y += f0.y;
        a1.x += f1.x; a1.y += f1.y;
    }
    uint2 o;
    o.x = h2u(__floats2half2_rn(a0.x, a0.y));
    o.y = h2u(__floats2half2_rn(a1.x, a1.y));
    out[(size_t)gw * 32 + lane] = o;
}

// ================= fp16 mma.sync (m16n8k16) fused MLP =================
#define HSTRIDE 136
#define SM_H   0
#define SM_W1  (128 * HSTRIDE * 2)
#define SM_W2  (2 * 128 * HSTRIDE * 2)
#define SM_B   (3 * 128 * HSTRIDE * 2)
#define MLP_SMEM (SM_B + 1024)

__device__ __forceinline__ void mma16n8k16(float* c,
                                           uint32_t a0, uint32_t a1, uint32_t a2, uint32_t a3,
                                           uint32_t b0, uint32_t b1) {
    asm volatile(
        "mma.sync.aligned.m16n8k16.row.col.f32.f16.f16.f32 "
        "{%0,%1,%2,%3}, {%4,%5,%6,%7}, {%8,%9}, {%0,%1,%2,%3};"
        : "+f"(c[0]), "+f"(c[1]), "+f"(c[2]), "+f"(c[3])
        : "r"(a0), "r"(a1), "r"(a2), "r"(a3), "r"(b0), "r"(b1));
}

template<bool OUT_H>
__global__ void __launch_bounds__(256, 2)
mlp_mma(const uint2* __restrict__ hin,
        const float* __restrict__ W1, const float* __restrict__ b1,
        const float* __restrict__ W2, const float* __restrict__ b2,
        void* __restrict__ outv, int relu_out)
{
    extern __shared__ __align__(16) char sm[];
    __half* sH  = (__half*)(sm + SM_H);
    __half* sW1 = (__half*)(sm + SM_W1);
    __half* sW2 = (__half*)(sm + SM_W2);
    float*  sB1 = (float*)(sm + SM_B);
    float*  sB2 = sB1 + 128;

    const int tid  = threadIdx.x;
    const int wid  = tid >> 5;
    const int lane = tid & 31;
    const int gid  = lane >> 2;
    const int tig  = lane & 3;
    const int fh   = wid & 1;
    const int sp   = wid >> 1;
    const int nbase = fh * 64;
    const int mbase = sp * 32;

    for (int i = tid; i < 8192; i += 256) {
        int k = (i >> 7) * 2, n = i & 127;
        float w1a = W1[k * 128 + n],  w1b = W1[(k + 1) * 128 + n];
        float w2a = W2[k * 128 + n],  w2b = W2[(k + 1) * 128 + n];
        *(uint32_t*)(sW1 + n * HSTRIDE + k) = h2u(__floats2half2_rn(w1a, w1b));
        *(uint32_t*)(sW2 + n * HSTRIDE + k) = h2u(__floats2half2_rn(w2a, w2b));
    }
    if (tid < 128) { sB1[tid] = b1[tid]; sB2[tid] = b2[tid]; }
    __syncthreads();

    const int ntiles = (N_NODES + 127) / 128;
    const __half* arow0 = sH + (mbase + gid) * HSTRIDE;
    const __half* arow1 = arow0 + 16 * HSTRIDE;

    for (int t = blockIdx.x; t < ntiles; t += gridDim.x) {
        const int row0 = t * 128;

        // ---- stage tile (fp16 raw copy, zero-padded) ----
        for (int i = tid; i < 128 * 32; i += 256) {
            int r = i >> 5, c4 = i & 31;
            int gr = row0 + r;
            uint2 p = make_uint2(0u, 0u);
            if (gr < N_NODES) p = __ldg(&hin[(size_t)gr * 32 + c4]);
            *(uint2*)(sH + r * HSTRIDE + c4 * 4) = p;
        }
        __syncthreads();

        float acc[2][8][4];
        #pragma unroll
        for (int s = 0; s < 2; s++)
            #pragma unroll
            for (int f = 0; f < 8; f++)
                acc[s][f][0] = acc[s][f][1] = acc[s][f][2] = acc[s][f][3] = 0.f;

        // ---- GEMM1 ----
        #pragma unroll
        for (int ks = 0; ks < 8; ks++) {
            const int k0 = ks * 16;
            uint32_t a00 = *(const uint32_t*)(arow0 + k0 + 2 * tig);
            uint32_t a01 = *(const uint32_t*)(arow0 + 8 * HSTRIDE + k0 + 2 * tig);
            uint32_t a02 = *(const uint32_t*)(arow0 + k0 + 2 * tig + 8);
            uint32_t a03 = *(const uint32_t*)(arow0 + 8 * HSTRIDE + k0 + 2 * tig + 8);
            uint32_t a10 = *(const uint32_t*)(arow1 + k0 + 2 * tig);
            uint32_t a11 = *(const uint32_t*)(arow1 + 8 * HSTRIDE + k0 + 2 * tig);
            uint32_t a12 = *(const uint32_t*)(arow1 + k0 + 2 * tig + 8);
            uint32_t a13 = *(const uint32_t*)(arow1 + 8 * HSTRIDE + k0 + 2 * tig + 8);
            const __half* bp = sW1 + (nbase + gid) * HSTRIDE + k0 + 2 * tig;
            #pragma unroll
            for (int f = 0; f < 8; f++) {
                uint32_t b0 = *(const uint32_t*)(bp + f * 8 * HSTRIDE);
                uint32_t b1 = *(const uint32_t*)(bp + f * 8 * HSTRIDE + 8);
                mma16n8k16(acc[0][f], a00, a01, a02, a03, b0, b1);
                mma16n8k16(acc[1][f], a10, a11, a12, a13, b0, b1);
            }
        }

        // ---- epilogue1: relu(acc + b1) -> sH (fp16) ----
        __syncthreads();
        #pragma unroll
        for (int s = 0; s < 2; s++) {
            int ra = mbase + s * 16 + gid;
            #pragma unroll
            for (int f = 0; f < 8; f++) {
                int col = nbase + 8 * f + 2 * tig;
                float v0 = fmaxf(acc[s][f][0] + sB1[col],     0.f);
                float v1 = fmaxf(acc[s][f][1] + sB1[col + 1], 0.f);
                float v2 = fmaxf(acc[s][f][2] + sB1[col],     0.f);
                float v3 = fmaxf(acc[s][f][3] + sB1[col + 1], 0.f);
                *(uint32_t*)(sH + ra * HSTRIDE + col)       = h2u(__floats2half2_rn(v0, v1));
                *(uint32_t*)(sH + (ra + 8) * HSTRIDE + col) = h2u(__floats2half2_rn(v2, v3));
            }
        }
        __syncthreads();

        #pragma unroll
        for (int s = 0; s < 2; s++)
            #pragma unroll
            for (int f = 0; f < 8; f++)
                acc[s][f][0] = acc[s][f][1] = acc[s][f][2] = acc[s][f][3] = 0.f;

        // ---- GEMM2 ----
        #pragma unroll
        for (int ks = 0; ks < 8; ks++) {
            const int k0 = ks * 16;
            uint32_t a00 = *(const uint32_t*)(arow0 + k0 + 2 * tig);
            uint32_t a01 = *(const uint32_t*)(arow0 + 8 * HSTRIDE + k0 + 2 * tig);
            uint32_t a02 = *(const uint32_t*)(arow0 + k0 + 2 * tig + 8);
            uint32_t a03 = *(const uint32_t*)(arow0 + 8 * HSTRIDE + k0 + 2 * tig + 8);
            uint32_t a10 = *(const uint32_t*)(arow1 + k0 + 2 * tig);
            uint32_t a11 = *(const uint32_t*)(arow1 + 8 * HSTRIDE + k0 + 2 * tig);
            uint32_t a12 = *(const uint32_t*)(arow1 + k0 + 2 * tig + 8);
            uint32_t a13 = *(const uint32_t*)(arow1 + 8 * HSTRIDE + k0 + 2 * tig + 8);
            const __half* bp = sW2 + (nbase + gid) * HSTRIDE + k0 + 2 * tig;
            #pragma unroll
            for (int f = 0; f < 8; f++) {
                uint32_t b0 = *(const uint32_t*)(bp + f * 8 * HSTRIDE);
                uint32_t b1 = *(const uint32_t*)(bp + f * 8 * HSTRIDE + 8);
                mma16n8k16(acc[0][f], a00, a01, a02, a03, b0, b1);
                mma16n8k16(acc[1][f], a10, a11, a12, a13, b0, b1);
            }
        }

        // ---- epilogue2: acc + b2 (+relu) -> gmem ----
        #pragma unroll
        for (int s = 0; s < 2; s++) {
            const int gr0 = row0 + mbase + s * 16 + gid;
            const int gr1 = gr0 + 8;
            #pragma unroll
            for (int f = 0; f < 8; f++) {
                int col = nbase + 8 * f + 2 * tig;
                if (gr0 < N_NODES) {
                    float v0 = acc[s][f][0] + sB2[col];
                    float v1 = acc[s][f][1] + sB2[col + 1];
                    if (relu_out) { v0 = fmaxf(v0, 0.f); v1 = fmaxf(v1, 0.f); }
                    if (OUT_H)
                        *(uint32_t*)((__half*)outv + (size_t)gr0 * DIM + col) =
                            h2u(__floats2half2_rn(v0, v1));
                    else
                        *(float2*)((float*)outv + (size_t)gr0 * DIM + col) = make_float2(v0, v1);
                }
                if (gr1 < N_NODES) {
                    float v2 = acc[s][f][2] + sB2[col];
                    float v3 = acc[s][f][3] + sB2[col + 1];
                    if (relu_out) { v2 = fmaxf(v2, 0.f); v3 = fmaxf(v3, 0.f); }
                    if (OUT_H)
                        *(uint32_t*)((__half*)outv + (size_t)gr1 * DIM + col) =
                            h2u(__floats2half2_rn(v2, v3));
                    else
                        *(float2*)((float*)outv + (size_t)gr1 * DIM + col) = make_float2(v2, v3);
                }
            }
        }
        __syncthreads();
    }
}

// ---------------- launch ----------------
extern "C" void kernel_launch(void* const* d_in, const int* in_sizes, int n_in,
                              void* d_out, int out_size)
{
    const float* x  = (const float*)d_in[0];
    const int*   ei = (const int*)d_in[1];
    const float* W1 = (const float*)d_in[2];
    const float* b1 = (const float*)d_in[3];
    const float* W2 = (const float*)d_in[4];
    const float* b2 = (const float*)d_in[5];
    float* out = (float*)d_out;

    static float* bufA = nullptr;
    static float* bufB = nullptr;
    static int*   degp = nullptr;
    if (!bufA) {
        void *pA, *pB, *pD;
        cudaGetSymbolAddress(&pA, g_bufA);
        cudaGetSymbolAddress(&pB, g_bufB);
        cudaGetSymbolAddress(&pD, g_deg);
        bufA = (float*)pA;
        bufB = (float*)pB;
        degp = (int*)pD;
        cudaFuncSetAttribute(mlp_mma<true>,
                             cudaFuncAttributeMaxDynamicSharedMemorySize, MLP_SMEM);
        cudaFuncSetAttribute(mlp_mma<false>,
                             cudaFuncAttributeMaxDynamicSharedMemorySize, MLP_SMEM);
    }

    // CSR build + x->fp16 (bufA holds x16)
    cudaMemsetAsync(degp, 0, N_NODES * sizeof(int), 0);
    count_convert_kernel<<<COUNT_BLOCKS + CONV_BLOCKS, 256>>>(ei, (const float4*)x, (uint2*)bufA);
    scan_kernel<<<1, 1024>>>();
    fill_kernel<<<COUNT_BLOCKS, 256>>>(ei);

    const int agg_grid = (N_NODES * 32 + 255) / 256;
    const int mlp_grid = 296;   // 2 CTAs/SM x 148 SMs

    // layer 0: fp16 throughout (x16 in bufA)
    agg_kernel_h<<<agg_grid, 256>>>((const uint2*)bufA, (uint2*)bufB);
    mlp_mma<true><<<mlp_grid, 256, MLP_SMEM>>>((const uint2*)bufB, W1, b1, W2, b2, bufA, 1);
    // layer 1
    agg_kernel_h<<<agg_grid, 256>>>((const uint2*)bufA, (uint2*)bufB);
    mlp_mma<true><<<mlp_grid, 256, MLP_SMEM>>>((const uint2*)bufB, W1 + 16384, b1 + 128,
                                               W2 + 16384, b2 + 128, bufA, 1);
    // layer 2: fp32 out
    agg_kernel_h<<<agg_grid, 256>>>((const uint2*)bufA, (uint2*)bufB);
    mlp_mma<false><<<mlp_grid, 256, MLP_SMEM>>>((const uint2*)bufB, W1 + 32768, b1 + 256,
                                                W2 + 32768, b2 + 256, out, 0);
}